// round 8
// baseline (speedup 1.0000x reference)
#include <cuda_runtime.h>
#include <cstddef>

#define N_NODES  50000
#define N_EDGES  800000
#define N_GRAPHS 1024
#define HID      128
#define D_SMILES 768
#define N_CLASSES 12

// ---------------- scratch (device globals; no allocation allowed) ----------
__device__ float g_h[(size_t)N_NODES * HID];     // GEMM output / gather source
__device__ float g_agg[(size_t)N_NODES * HID];   // scatter accumulator
__device__ float g_deg[N_NODES];
__device__ float g_dinv[N_NODES];
__device__ float g_t1[(size_t)N_GRAPHS * HID];       // smiles hidden (raw)
__device__ float g_comb[(size_t)N_GRAPHS * 2 * HID]; // [s | g]
__device__ float g_cnt[N_GRAPHS];
__device__ float g_fused[(size_t)N_GRAPHS * HID];

// ---------------- degree / norm -------------------------------------------
__global__ void deg_init_kernel() {
    int i = blockIdx.x * blockDim.x + threadIdx.x;
    if (i < N_NODES) g_deg[i] = 1.0f;  // self loop
}

__global__ void deg_count_kernel(const int* __restrict__ dst) {
    int e = blockIdx.x * blockDim.x + threadIdx.x;
    if (e < N_EDGES) atomicAdd(&g_deg[dst[e]], 1.0f);
}

__global__ void dinv_kernel() {
    int i = blockIdx.x * blockDim.x + threadIdx.x;
    if (i < N_NODES) g_dinv[i] = rsqrtf(g_deg[i]);
}

// ---------------- GEMM: C[M,128] = op(A[M,K]) @ B[K,128] ------------------
// op(a) = relu(a + bias_in[k]) when bias_in != nullptr, else a.
// Output: += bias_out, optional relu. C row stride = ldc.
// If Cagg != nullptr, additionally writes Cagg[m, n] = C[m, n] * dinv[m]^2
// (the GCN self-loop message), eliminating a separate agg-init pass.
__global__ __launch_bounds__(512)
void gemm128_kernel(const float* __restrict__ A, const float* __restrict__ B,
                    float* __restrict__ C, int M, int K, int ldc,
                    const float* __restrict__ bias_in,
                    const float* __restrict__ bias_out, int relu_out,
                    float* __restrict__ Cagg)
{
    __shared__ float sA[64][36];    // row stride 36 floats (144B, 16B aligned)
    __shared__ float sB[32][128];

    const int tid = threadIdx.x;
    const int tx = tid & 31;        // 32 threads along N, 4 cols each
    const int ty = tid >> 5;        // 16 threads along M, 4 rows each
    const int m0 = blockIdx.x * 64;

    float acc[4][4] = {};

    for (int k0 = 0; k0 < K; k0 += 32) {
        // Load A tile 64x32 (coalesced; warp = one row, consecutive k)
        #pragma unroll
        for (int it = 0; it < 4; ++it) {
            int m  = it * 16 + (tid >> 5);
            int kk = tid & 31;
            int gm = m0 + m;
            float v = 0.0f;
            if (gm < M) v = A[(size_t)gm * K + k0 + kk];
            if (bias_in) v = fmaxf(v + bias_in[k0 + kk], 0.0f);
            sA[m][kk] = v;
        }
        // Load B tile 32x128 (coalesced)
        #pragma unroll
        for (int it = 0; it < 8; ++it) {
            int kk = it * 4 + (tid >> 7);
            int n  = tid & 127;
            sB[kk][n] = B[(size_t)(k0 + kk) * HID + n];
        }
        __syncthreads();

        #pragma unroll
        for (int kb = 0; kb < 32; kb += 4) {
            float4 a[4], b[4];
            #pragma unroll
            for (int i = 0; i < 4; ++i)
                a[i] = *(const float4*)&sA[ty * 4 + i][kb];   // broadcast LDS.128
            #pragma unroll
            for (int j = 0; j < 4; ++j)
                b[j] = *(const float4*)&sB[kb + j][tx * 4];   // conflict-free LDS.128
            #pragma unroll
            for (int i = 0; i < 4; ++i) {
                float av[4] = {a[i].x, a[i].y, a[i].z, a[i].w};
                #pragma unroll
                for (int j = 0; j < 4; ++j) {
                    acc[i][0] += av[j] * b[j].x;
                    acc[i][1] += av[j] * b[j].y;
                    acc[i][2] += av[j] * b[j].z;
                    acc[i][3] += av[j] * b[j].w;
                }
            }
        }
        __syncthreads();
    }

    #pragma unroll
    for (int i = 0; i < 4; ++i) {
        int gm = m0 + ty * 4 + i;
        if (gm < M) {
            float4 o;
            o.x = acc[i][0]; o.y = acc[i][1]; o.z = acc[i][2]; o.w = acc[i][3];
            if (bias_out) {
                o.x += bias_out[tx * 4 + 0];
                o.y += bias_out[tx * 4 + 1];
                o.z += bias_out[tx * 4 + 2];
                o.w += bias_out[tx * 4 + 3];
            }
            if (relu_out) {
                o.x = fmaxf(o.x, 0.0f); o.y = fmaxf(o.y, 0.0f);
                o.z = fmaxf(o.z, 0.0f); o.w = fmaxf(o.w, 0.0f);
            }
            *(float4*)&C[(size_t)gm * ldc + tx * 4] = o;
            if (Cagg) {
                float w = g_dinv[gm];
                w = w * w;
                float4 q;
                q.x = o.x * w; q.y = o.y * w; q.z = o.z * w; q.w = o.w * w;
                *(float4*)&Cagg[(size_t)gm * HID + tx * 4] = q;
            }
        }
    }
}

// ---------------- edge scatter: agg[dst] += h[src] * dinv[s]*dinv[d] ------
__global__ __launch_bounds__(256)
void scatter_kernel(const int* __restrict__ src, const int* __restrict__ dst)
{
    int e = blockIdx.x * 8 + (threadIdx.x >> 5);
    if (e >= N_EDGES) return;
    int lane = threadIdx.x & 31;
    int s = __ldg(&src[e]);
    int d = __ldg(&dst[e]);
    float w = __ldg(&g_dinv[s]) * __ldg(&g_dinv[d]);
    float4 v = __ldg((const float4*)(g_h + (size_t)s * HID) + lane);
    v.x *= w; v.y *= w; v.z *= w; v.w *= w;
    float4* a = (float4*)(g_agg + (size_t)d * HID) + lane;
    asm volatile("red.global.add.v4.f32 [%0], {%1,%2,%3,%4};"
                 :: "l"(a), "f"(v.x), "f"(v.y), "f"(v.z), "f"(v.w)
                 : "memory");
}

// ---------------- pooling --------------------------------------------------
__global__ void pool_zero_kernel() {
    int i = blockIdx.x * blockDim.x + threadIdx.x;
    if (i < N_GRAPHS * HID) g_comb[(size_t)(i >> 7) * 256 + HID + (i & 127)] = 0.0f;
    if (i < N_GRAPHS) g_cnt[i] = 0.0f;
}

__global__ __launch_bounds__(128)
void pool_acc_kernel(const int* __restrict__ batch, const float* __restrict__ bg2)
{
    int node = blockIdx.x;
    int f = threadIdx.x;
    int b = __ldg(&batch[node]);
    float v = fmaxf(g_agg[(size_t)node * HID + f] + bg2[f], 0.0f);
    atomicAdd(&g_comb[(size_t)b * 256 + HID + f], v);
    if (f == 0) atomicAdd(&g_cnt[b], 1.0f);
}

__global__ void pool_norm_kernel() {
    int i = blockIdx.x * blockDim.x + threadIdx.x;
    if (i >= N_GRAPHS * HID) return;
    int b = i >> 7;
    float c = fmaxf(g_cnt[b], 1.0f);
    g_comb[(size_t)b * 256 + HID + (i & 127)] *= (1.0f / c);
}

// ---------------- output head: out = fused @ Wo + bo ----------------------
__global__ void out_gemm_kernel(const float* __restrict__ Wo,
                                const float* __restrict__ bo,
                                float* __restrict__ out)
{
    int i = blockIdx.x * blockDim.x + threadIdx.x;
    if (i >= N_GRAPHS * N_CLASSES) return;
    int r = i / N_CLASSES, c = i % N_CLASSES;
    float s = bo[c];
    const float* fr = g_fused + (size_t)r * HID;
    #pragma unroll 16
    for (int k = 0; k < HID; ++k)
        s += fr[k] * __ldg(&Wo[k * N_CLASSES + c]);
    out[i] = s;
}

// ---------------- launch ---------------------------------------------------
static float* sym_addr(const void* symbol) {
    void* p = nullptr;
    cudaGetSymbolAddress(&p, symbol);
    return (float*)p;
}

extern "C" void kernel_launch(void* const* d_in, const int* in_sizes, int n_in,
                              void* d_out, int out_size)
{
    const float* smiles = (const float*)d_in[0];
    const float* x      = (const float*)d_in[1];
    const int*   ei     = (const int*)d_in[2];
    const int*   batch  = (const int*)d_in[3];
    const float* Ws1 = (const float*)d_in[4];
    const float* bs1 = (const float*)d_in[5];
    const float* Ws2 = (const float*)d_in[6];
    const float* bs2 = (const float*)d_in[7];
    const float* Wg1 = (const float*)d_in[8];
    const float* bg1 = (const float*)d_in[9];
    const float* Wg2 = (const float*)d_in[10];
    const float* bg2 = (const float*)d_in[11];
    const float* Wf  = (const float*)d_in[12];
    const float* bf  = (const float*)d_in[13];
    const float* Wo  = (const float*)d_in[14];
    const float* bo  = (const float*)d_in[15];
    float* out = (float*)d_out;

    const int* src = ei;
    const int* dst = ei + N_EDGES;

    float* p_h     = sym_addr(g_h);
    float* p_agg   = sym_addr(g_agg);
    float* p_t1    = sym_addr(g_t1);
    float* p_comb  = sym_addr(g_comb);
    float* p_fused = sym_addr(g_fused);

    // degree + symmetric norm (edge-structure only; once per call)
    deg_init_kernel<<<(N_NODES + 255) / 256, 256>>>();
    deg_count_kernel<<<N_EDGES / 256, 256>>>(dst);
    dinv_kernel<<<(N_NODES + 255) / 256, 256>>>();

    const int gemm_grid_nodes = (N_NODES + 63) / 64;   // 782

    // GCN layer 1 (h = x @ Wg1; agg = h * dinv^2 fused into epilogue)
    gemm128_kernel<<<gemm_grid_nodes, 512>>>(x, Wg1, p_h, N_NODES, HID, HID,
                                             nullptr, nullptr, 0, p_agg);
    scatter_kernel<<<N_EDGES / 8, 256>>>(src, dst);

    // GCN layer 2 (relu(agg + bg1) fused into A-operand load; agg-init fused)
    gemm128_kernel<<<gemm_grid_nodes, 512>>>(p_agg, Wg2, p_h, N_NODES, HID, HID,
                                             bg1, nullptr, 0, p_agg);
    scatter_kernel<<<N_EDGES / 8, 256>>>(src, dst);

    // global mean pool (relu(agg + bg2) fused) -> comb[:, 128:256]
    pool_zero_kernel<<<(N_GRAPHS * HID + 255) / 256, 256>>>();
    pool_acc_kernel<<<N_NODES, 128>>>(batch, bg2);
    pool_norm_kernel<<<(N_GRAPHS * HID + 255) / 256, 256>>>();

    // SMILES MLP -> comb[:, 0:128]
    gemm128_kernel<<<N_GRAPHS / 64, 512>>>(smiles, Ws1, p_t1, N_GRAPHS, D_SMILES,
                                           HID, nullptr, nullptr, 0, nullptr);
    gemm128_kernel<<<N_GRAPHS / 64, 512>>>(p_t1, Ws2, p_comb, N_GRAPHS, HID,
                                           2 * HID, bs1, bs2, 0, nullptr);

    // fusion: fused = relu(comb @ Wf + bf)
    gemm128_kernel<<<N_GRAPHS / 64, 512>>>(p_comb, Wf, p_fused, N_GRAPHS, 2 * HID,
                                           HID, nullptr, bf, 1, nullptr);

    // head
    out_gemm_kernel<<<(N_GRAPHS * N_CLASSES + 255) / 256, 256>>>(Wo, bo, out);
}

// round 11
// speedup vs baseline: 1.2177x; 1.2177x over previous
#include <cuda_runtime.h>
#include <cstddef>

#define N_NODES  50000
#define N_EDGES  800000
#define N_GRAPHS 1024
#define HID      128
#define D_SMILES 768
#define N_CLASSES 12

// ---------------- scratch (device globals; no allocation allowed) ----------
__device__ float g_h[(size_t)N_NODES * HID];     // GEMM output / gather source
__device__ float g_agg[(size_t)N_NODES * HID];   // aggregation output
__device__ float g_dinv[N_NODES];
__device__ int   g_degi[N_NODES];
__device__ int   g_csr_ptr[N_NODES + 1];
__device__ int   g_cursor[N_NODES];
__device__ int   g_csr_src[N_EDGES];
__device__ float g_csr_w[N_EDGES];
__device__ float g_t1[(size_t)N_GRAPHS * HID];       // smiles hidden (raw)
__device__ float g_comb[(size_t)N_GRAPHS * 2 * HID]; // [s | g]
__device__ float g_cnt[N_GRAPHS];
__device__ float g_fused[(size_t)N_GRAPHS * HID];

// ---------------- degree / norm / CSR build -------------------------------
__global__ void degi_zero_kernel() {
    int i = blockIdx.x * blockDim.x + threadIdx.x;
    if (i < N_NODES) g_degi[i] = 0;
}

__global__ void deg_count_kernel(const int* __restrict__ dst) {
    int e = blockIdx.x * blockDim.x + threadIdx.x;
    if (e < N_EDGES) atomicAdd(&g_degi[dst[e]], 1);
}

__global__ void dinv_kernel() {
    int i = blockIdx.x * blockDim.x + threadIdx.x;
    if (i < N_NODES) g_dinv[i] = rsqrtf((float)g_degi[i] + 1.0f);  // +1 self loop
}

// Exclusive prefix sum of g_degi -> g_csr_ptr. One block, 1024 threads.
__global__ void scan_kernel() {
    __shared__ int warp_tot[32];
    __shared__ int s_carry;
    int tid = threadIdx.x, lane = tid & 31, wid = tid >> 5;
    if (tid == 0) s_carry = 0;
    __syncthreads();
    for (int base = 0; base < N_NODES; base += 1024) {
        int i = base + tid;
        int v = (i < N_NODES) ? g_degi[i] : 0;
        int x = v;
        #pragma unroll
        for (int o = 1; o < 32; o <<= 1) {
            int y = __shfl_up_sync(~0u, x, o);
            if (lane >= o) x += y;
        }
        if (lane == 31) warp_tot[wid] = x;
        __syncthreads();
        if (wid == 0) {
            int t = warp_tot[lane];
            #pragma unroll
            for (int o = 1; o < 32; o <<= 1) {
                int y = __shfl_up_sync(~0u, t, o);
                if (lane >= o) t += y;
            }
            warp_tot[lane] = t;
        }
        __syncthreads();
        int incl = x + (wid > 0 ? warp_tot[wid - 1] : 0);
        int carry = s_carry;
        if (i < N_NODES) g_csr_ptr[i] = carry + incl - v;   // exclusive
        __syncthreads();
        if (tid == 1023) s_carry = carry + warp_tot[31];
        __syncthreads();
    }
    if (threadIdx.x == 0) g_csr_ptr[N_NODES] = N_EDGES;
}

__global__ void cursor_copy_kernel() {
    int i = blockIdx.x * blockDim.x + threadIdx.x;
    if (i < N_NODES) g_cursor[i] = g_csr_ptr[i];
}

__global__ void csr_fill_kernel(const int* __restrict__ src,
                                const int* __restrict__ dst) {
    int e = blockIdx.x * blockDim.x + threadIdx.x;
    if (e >= N_EDGES) return;
    int s = __ldg(&src[e]);
    int d = __ldg(&dst[e]);
    int pos = atomicAdd(&g_cursor[d], 1);
    g_csr_src[pos] = s;
    g_csr_w[pos] = __ldg(&g_dinv[s]) * __ldg(&g_dinv[d]);
}

// ---------------- GEMM: C[M,128] = op(A[M,K]) @ B[K,128] ------------------
// op(a) = relu(a + bias_in[k]) when bias_in != nullptr, else a.
// Output: += bias_out, optional relu. C row stride = ldc.
__global__ __launch_bounds__(512)
void gemm128_kernel(const float* __restrict__ A, const float* __restrict__ B,
                    float* __restrict__ C, int M, int K, int ldc,
                    const float* __restrict__ bias_in,
                    const float* __restrict__ bias_out, int relu_out)
{
    __shared__ float sA[64][36];    // row stride 36 floats (144B, 16B aligned)
    __shared__ float sB[32][128];

    const int tid = threadIdx.x;
    const int tx = tid & 31;        // 32 threads along N, 4 cols each
    const int ty = tid >> 5;        // 16 threads along M, 4 rows each
    const int m0 = blockIdx.x * 64;

    float acc[4][4] = {};

    for (int k0 = 0; k0 < K; k0 += 32) {
        #pragma unroll
        for (int it = 0; it < 4; ++it) {
            int m  = it * 16 + (tid >> 5);
            int kk = tid & 31;
            int gm = m0 + m;
            float v = 0.0f;
            if (gm < M) v = A[(size_t)gm * K + k0 + kk];
            if (bias_in) v = fmaxf(v + bias_in[k0 + kk], 0.0f);
            sA[m][kk] = v;
        }
        #pragma unroll
        for (int it = 0; it < 8; ++it) {
            int kk = it * 4 + (tid >> 7);
            int n  = tid & 127;
            sB[kk][n] = B[(size_t)(k0 + kk) * HID + n];
        }
        __syncthreads();

        #pragma unroll
        for (int kb = 0; kb < 32; kb += 4) {
            float4 a[4], b[4];
            #pragma unroll
            for (int i = 0; i < 4; ++i)
                a[i] = *(const float4*)&sA[ty * 4 + i][kb];
            #pragma unroll
            for (int j = 0; j < 4; ++j)
                b[j] = *(const float4*)&sB[kb + j][tx * 4];
            #pragma unroll
            for (int i = 0; i < 4; ++i) {
                float av[4] = {a[i].x, a[i].y, a[i].z, a[i].w};
                #pragma unroll
                for (int j = 0; j < 4; ++j) {
                    acc[i][0] += av[j] * b[j].x;
                    acc[i][1] += av[j] * b[j].y;
                    acc[i][2] += av[j] * b[j].z;
                    acc[i][3] += av[j] * b[j].w;
                }
            }
        }
        __syncthreads();
    }

    #pragma unroll
    for (int i = 0; i < 4; ++i) {
        int gm = m0 + ty * 4 + i;
        if (gm < M) {
            float4 o;
            o.x = acc[i][0]; o.y = acc[i][1]; o.z = acc[i][2]; o.w = acc[i][3];
            if (bias_out) {
                o.x += bias_out[tx * 4 + 0];
                o.y += bias_out[tx * 4 + 1];
                o.z += bias_out[tx * 4 + 2];
                o.w += bias_out[tx * 4 + 3];
            }
            if (relu_out) {
                o.x = fmaxf(o.x, 0.0f); o.y = fmaxf(o.y, 0.0f);
                o.z = fmaxf(o.z, 0.0f); o.w = fmaxf(o.w, 0.0f);
            }
            *(float4*)&C[(size_t)gm * ldc + tx * 4] = o;
        }
    }
}

// ---------------- pull-mode aggregation (CSR) -----------------------------
// agg[d] = h[d]*dinv[d]^2 + sum_{e in CSR[d]} h[src[e]] * w[e]
__global__ __launch_bounds__(256)
void aggregate_kernel()
{
    int node = blockIdx.x * 8 + (threadIdx.x >> 5);
    if (node >= N_NODES) return;
    int lane = threadIdx.x & 31;

    int beg = __ldg(&g_csr_ptr[node]);
    int end = __ldg(&g_csr_ptr[node + 1]);

    float di = __ldg(&g_dinv[node]);
    float w0 = di * di;
    float4 acc = __ldg((const float4*)(g_h + (size_t)node * HID) + lane);
    acc.x *= w0; acc.y *= w0; acc.z *= w0; acc.w *= w0;

    int j = beg;
    for (; j + 1 < end; j += 2) {
        int   s0 = __ldg(&g_csr_src[j]);
        int   s1 = __ldg(&g_csr_src[j + 1]);
        float w0e = __ldg(&g_csr_w[j]);
        float w1e = __ldg(&g_csr_w[j + 1]);
        float4 v0 = __ldg((const float4*)(g_h + (size_t)s0 * HID) + lane);
        float4 v1 = __ldg((const float4*)(g_h + (size_t)s1 * HID) + lane);
        acc.x += v0.x * w0e + v1.x * w1e;
        acc.y += v0.y * w0e + v1.y * w1e;
        acc.z += v0.z * w0e + v1.z * w1e;
        acc.w += v0.w * w0e + v1.w * w1e;
    }
    if (j < end) {
        int   s0 = __ldg(&g_csr_src[j]);
        float we = __ldg(&g_csr_w[j]);
        float4 v0 = __ldg((const float4*)(g_h + (size_t)s0 * HID) + lane);
        acc.x += v0.x * we; acc.y += v0.y * we;
        acc.z += v0.z * we; acc.w += v0.w * we;
    }

    ((float4*)(g_agg + (size_t)node * HID))[lane] = acc;
}

// ---------------- pooling --------------------------------------------------
__global__ void pool_zero_kernel() {
    int i = blockIdx.x * blockDim.x + threadIdx.x;
    if (i < N_GRAPHS * HID) g_comb[(size_t)(i >> 7) * 256 + HID + (i & 127)] = 0.0f;
    if (i < N_GRAPHS) g_cnt[i] = 0.0f;
}

__global__ __launch_bounds__(128)
void pool_acc_kernel(const int* __restrict__ batch, const float* __restrict__ bg2)
{
    int node = blockIdx.x;
    int f = threadIdx.x;
    int b = __ldg(&batch[node]);
    float v = fmaxf(g_agg[(size_t)node * HID + f] + bg2[f], 0.0f);
    atomicAdd(&g_comb[(size_t)b * 256 + HID + f], v);
    if (f == 0) atomicAdd(&g_cnt[b], 1.0f);
}

__global__ void pool_norm_kernel() {
    int i = blockIdx.x * blockDim.x + threadIdx.x;
    if (i >= N_GRAPHS * HID) return;
    int b = i >> 7;
    float c = fmaxf(g_cnt[b], 1.0f);
    g_comb[(size_t)b * 256 + HID + (i & 127)] *= (1.0f / c);
}

// ---------------- output head: out = fused @ Wo + bo ----------------------
__global__ void out_gemm_kernel(const float* __restrict__ Wo,
                                const float* __restrict__ bo,
                                float* __restrict__ out)
{
    int i = blockIdx.x * blockDim.x + threadIdx.x;
    if (i >= N_GRAPHS * N_CLASSES) return;
    int r = i / N_CLASSES, c = i % N_CLASSES;
    float s = bo[c];
    const float* fr = g_fused + (size_t)r * HID;
    #pragma unroll 16
    for (int k = 0; k < HID; ++k)
        s += fr[k] * __ldg(&Wo[k * N_CLASSES + c]);
    out[i] = s;
}

// ---------------- launch ---------------------------------------------------
static float* sym_addr(const void* symbol) {
    void* p = nullptr;
    cudaGetSymbolAddress(&p, symbol);
    return (float*)p;
}

extern "C" void kernel_launch(void* const* d_in, const int* in_sizes, int n_in,
                              void* d_out, int out_size)
{
    const float* smiles = (const float*)d_in[0];
    const float* x      = (const float*)d_in[1];
    const int*   ei     = (const int*)d_in[2];
    const int*   batch  = (const int*)d_in[3];
    const float* Ws1 = (const float*)d_in[4];
    const float* bs1 = (const float*)d_in[5];
    const float* Ws2 = (const float*)d_in[6];
    const float* bs2 = (const float*)d_in[7];
    const float* Wg1 = (const float*)d_in[8];
    const float* bg1 = (const float*)d_in[9];
    const float* Wg2 = (const float*)d_in[10];
    const float* bg2 = (const float*)d_in[11];
    const float* Wf  = (const float*)d_in[12];
    const float* bf  = (const float*)d_in[13];
    const float* Wo  = (const float*)d_in[14];
    const float* bo  = (const float*)d_in[15];
    float* out = (float*)d_out;

    const int* src = ei;
    const int* dst = ei + N_EDGES;

    float* p_h     = sym_addr(g_h);
    float* p_agg   = sym_addr(g_agg);
    float* p_t1    = sym_addr(g_t1);
    float* p_comb  = sym_addr(g_comb);
    float* p_fused = sym_addr(g_fused);

    // ----- CSR build (per call; edge structure only) -----
    degi_zero_kernel<<<(N_NODES + 255) / 256, 256>>>();
    deg_count_kernel<<<N_EDGES / 256, 256>>>(dst);
    dinv_kernel<<<(N_NODES + 255) / 256, 256>>>();
    scan_kernel<<<1, 1024>>>();
    cursor_copy_kernel<<<(N_NODES + 255) / 256, 256>>>();
    csr_fill_kernel<<<N_EDGES / 256, 256>>>(src, dst);

    const int gemm_grid_nodes = (N_NODES + 63) / 64;   // 782
    const int agg_grid = (N_NODES + 7) / 8;            // 6250

    // GCN layer 1
    gemm128_kernel<<<gemm_grid_nodes, 512>>>(x, Wg1, p_h, N_NODES, HID, HID,
                                             nullptr, nullptr, 0);
    aggregate_kernel<<<agg_grid, 256>>>();

    // GCN layer 2 (relu(agg + bg1) fused into A-operand load)
    gemm128_kernel<<<gemm_grid_nodes, 512>>>(p_agg, Wg2, p_h, N_NODES, HID, HID,
                                             bg1, nullptr, 0);
    aggregate_kernel<<<agg_grid, 256>>>();

    // global mean pool (relu(agg + bg2) fused) -> comb[:, 128:256]
    pool_zero_kernel<<<(N_GRAPHS * HID + 255) / 256, 256>>>();
    pool_acc_kernel<<<N_NODES, 128>>>(batch, bg2);
    pool_norm_kernel<<<(N_GRAPHS * HID + 255) / 256, 256>>>();

    // SMILES MLP -> comb[:, 0:128]
    gemm128_kernel<<<N_GRAPHS / 64, 512>>>(smiles, Ws1, p_t1, N_GRAPHS, D_SMILES,
                                           HID, nullptr, nullptr, 0);
    gemm128_kernel<<<N_GRAPHS / 64, 512>>>(p_t1, Ws2, p_comb, N_GRAPHS, HID,
                                           2 * HID, bs1, bs2, 0);

    // fusion: fused = relu(comb @ Wf + bf)
    gemm128_kernel<<<N_GRAPHS / 64, 512>>>(p_comb, Wf, p_fused, N_GRAPHS, 2 * HID,
                                           HID, nullptr, bf, 1);

    // head
    out_gemm_kernel<<<(N_GRAPHS * N_CLASSES + 255) / 256, 256>>>(Wo, bo, out);
}